// round 12
// baseline (speedup 1.0000x reference)
#include <cuda_runtime.h>
#include <math_constants.h>

#define HH 1024
#define WW 1024
#define NB 16
#define NPIX (NB * HH * WW)
#define TH 32
#define FULLM 0xffffffffu

// padded scratch geometry: logical (r,c), r in [-8,1031], c in [-8,1095]
#define PADT 8
#define PADL 8
#define PW   1104          // 8 + 1024 + 72
#define PH   1040          // 8 + 1024 + 8
#define PIMG (PH * PW)     // floats per padded image

__device__ __align__(256) float g_bufA[NB * PIMG];
__device__ __align__(256) float g_bufB[NB * PIMG];

#define C1 (1.0f / 24.0f)
#define C3 (3.0f / 24.0f)
#define C7 (7.0f / 24.0f)
#define NEGINF (-CUDART_INF_F)

typedef unsigned long long u64;

#define PK2(d, lo, hi)  asm("mov.b64 %0, {%1, %2};" : "=l"(d) : "f"(lo), "f"(hi))
#define UPK2(lo, hi, s) asm("mov.b64 {%0, %1}, %2;" : "=f"(lo), "=f"(hi) : "l"(s))
#define ADD2(d, a, b)   asm("add.rn.f32x2 %0, %1, %2;" : "=l"(d) : "l"(a), "l"(b))
#define ACC2(d, b)      asm("add.rn.f32x2 %0, %0, %1;" : "+l"(d) : "l"(b))
#define MUL2(d, a, b)   asm("mul.rn.f32x2 %0, %1, %2;" : "=l"(d) : "l"(a), "l"(b))
#define FMA2(d, a, b, c) asm("fma.rn.f32x2 %0, %1, %2, %3;" : "=l"(d) : "l"(a), "l"(b), "l"(c))

// ---- packed filter + ring accumulate; returns completed slot in raw[4] ----
template<int U>
__device__ __forceinline__ void filt(const float w[10], u64 a[7][2],
                                     u64 kC1, u64 kC3, u64 kM7, u64 kM1,
                                     float raw[4])
{
    u64 P[9];
    #pragma unroll
    for (int j = 0; j < 9; ++j) PK2(P[j], w[j], w[j + 1]);

    #pragma unroll
    for (int p = 0; p < 2; ++p) {
        const int o = 2 * p;
        u64 t1, Pt, Puu, Pvv, Px2;
        ADD2(t1, P[2 + o], P[3 + o]);
        ADD2(Pt, t1, P[4 + o]);
        ADD2(Puu, P[1 + o], P[5 + o]);
        ADD2(Pvv, P[0 + o], P[6 + o]);
        ADD2(Px2, P[2 + o], P[4 + o]);

        u64 hA, hB, hC, hD, m1, m2, m3, i1, i2, i3;
        MUL2(hA, kC1, Pt);
        MUL2(m1, kC1, Puu);
        FMA2(hB, kC3, Pt, m1);
        MUL2(m2, kC1, P[0 + o]);
        FMA2(i1, kM7, P[3 + o], m2);
        FMA2(hC, kC3, Puu, i1);
        MUL2(m3, kC1, Pvv);
        FMA2(i2, kM7, Px2, m3);
        FMA2(i3, kC3, Puu, i2);
        FMA2(hD, kM1, P[3 + o], i3);

        ACC2(a[(U + 0) % 7][p], hA);
        ACC2(a[(U + 1) % 7][p], hB);
        ACC2(a[(U + 2) % 7][p], hC);
        ACC2(a[(U + 3) % 7][p], hD);
        ACC2(a[(U + 4) % 7][p], hC);
        ACC2(a[(U + 5) % 7][p], hB);
        ACC2(a[(U + 6) % 7][p], hA);
    }
    UPK2(raw[0], raw[1], a[U % 7][0]);
    UPK2(raw[2], raw[3], a[U % 7][1]);
    a[U % 7][0] = 0ull;
    a[U % 7][1] = 0ull;
}

struct StI {
    u64 a[7][2];
    float cp[4], pm[4];
    int bpp1, bpp2;      // FIN: byte-packed bit history
};

// ===== universal step: 3-LDG window, optional guards (stage1 edge) and masks =====
template<int U, bool FIN, bool VM, bool WR, bool MX, bool MY, bool GUARD, int SSTR>
__device__ __forceinline__ void step_u(StI& s,
                                       float4& L, float4& M, float4& R,
                                       const float*& p0, int& rload, int& cr,
                                       float*& wp, const bool cv[4],
                                       bool Lok, bool Mok, bool Rok,
                                       bool writeok, int dup,
                                       u64 kC1, u64 kC3, u64 kM7, u64 kM1)
{
    constexpr int WSTR = FIN ? WW : PW;
    const float4 Z = make_float4(0.f, 0.f, 0.f, 0.f);

    float w[10] = { L.y, L.z, L.w, M.x, M.y, M.z, M.w, R.x, R.y, R.z };
    if (GUARD) {
        bool rv = (unsigned)rload < (unsigned)HH;
        L = (rv && Lok) ? *reinterpret_cast<const float4*>(p0 - 4) : Z;
        M = (rv && Mok) ? *reinterpret_cast<const float4*>(p0)     : Z;
        R = (rv && Rok) ? *reinterpret_cast<const float4*>(p0 + 4) : Z;
        ++rload;
    } else {
        L = *reinterpret_cast<const float4*>(p0 - 4);
        M = *reinterpret_cast<const float4*>(p0);
        R = *reinterpret_cast<const float4*>(p0 + 4);
    }
    p0 += SSTR;

    float raw[4];
    filt<U>(w, s.a, kC1, kC3, kM7, kM1, raw);

    if (MY) ++cr;

    if (VM) {
        float cur[4];
        if (MX || MY) {
            bool rv2 = !MY || ((unsigned)cr < (unsigned)HH);
            #pragma unroll
            for (int k = 0; k < 4; ++k) {
                bool ok = rv2 && (!MX || cv[k]);
                cur[k] = ok ? raw[k] : NEGINF;
            }
        } else {
            #pragma unroll
            for (int k = 0; k < 4; ++k) cur[k] = raw[k];
        }
        float vm[4];
        #pragma unroll
        for (int k = 0; k < 4; ++k) {
            vm[k]  = fmaxf(s.pm[k], cur[k]);
            s.pm[k] = fmaxf(cur[k], s.cp[k]);
            s.cp[k] = cur[k];
        }
        float vmL = __shfl_up_sync(FULLM, vm[3], 1);
        float vmR = __shfl_down_sync(FULLM, vm[0], 1);
        float m0 = fmaxf(vmL,   fmaxf(vm[0], vm[1]));
        float m1 = fmaxf(vm[0], fmaxf(vm[1], vm[2]));
        float m2 = fmaxf(vm[1], fmaxf(vm[2], vm[3]));
        float m3 = fmaxf(vm[2], fmaxf(vm[3], vmR));

        if (!FIN) {
            if (WR && writeok)
                *reinterpret_cast<float4*>(wp) = make_float4(m0, m1, m2, m3);
        } else {
            // binary bits exist only for in-image rows AND columns (avgpool 0-pad)
            bool bv = !MY || ((unsigned)(cr - 1) < (unsigned)HH);
            int b0 = (bv && (!MX || cv[0]) && m0 > 0.5f) ? 1 : 0;
            int b1 = (bv && (!MX || cv[1]) && m1 > 0.5f) ? 1 : 0;
            int b2 = (bv && (!MX || cv[2]) && m2 > 0.5f) ? 1 : 0;
            int b3 = (bv && (!MX || cv[3]) && m3 > 0.5f) ? 1 : 0;
            int bp = b0 | (b1 << 8) | (b2 << 16) | (b3 << 24);
            int sp_ = s.bpp2 + s.bpp1 + bp;     // per-byte counts <= 3, carry-free
            s.bpp2 = s.bpp1; s.bpp1 = bp;
            int sLp = __shfl_up_sync(FULLM, sp_, 1);
            int sRp = __shfl_down_sync(FULLM, sp_, 1);
            if (WR && writeok) {
                unsigned u = (unsigned)sp_;
                int s0 = u & 0xFF, s1 = (u >> 8) & 0xFF,
                    s2 = (u >> 16) & 0xFF, s3 = u >> 24;
                int n0 = (int)(((unsigned)sLp) >> 24) + s0 + s1;
                int n1 = s0 + s1 + s2;
                int n2 = s1 + s2 + s3;
                int n3 = s2 + s3 + (sRp & 0xFF);
                float4 o = make_float4(n0 >= 8 ? 1.f : 0.f, n1 >= 8 ? 1.f : 0.f,
                                       n2 >= 8 ? 1.f : 0.f, n3 >= 8 ? 1.f : 0.f);
                *reinterpret_cast<float4*>(wp) = o;
                if (dup) *reinterpret_cast<float4*>(wp + NPIX) = o;
            }
        }
        wp += WSTR;
    }
}

template<bool FIN, bool MX, bool MY, bool GUARD, int SSTR>
__device__ __forceinline__ void run_u(const float* sp, float* dp, int c0, int Y0,
                                      int lane, int dup)
{
    constexpr int WSTR = FIN ? WW : PW;
    const float4 Z = make_float4(0.f, 0.f, 0.f, 0.f);
    const bool writeok = (lane >= 1) && (lane <= 30) && ((unsigned)c0 <= 1020u);
    bool cv[4];
    #pragma unroll
    for (int k = 0; k < 4; ++k) cv[k] = (unsigned)(c0 + k) < (unsigned)WW;
    const bool Lok = (unsigned)(c0 - 4) < (unsigned)WW;
    const bool Mok = (unsigned)c0 < (unsigned)WW;
    const bool Rok = (unsigned)(c0 + 4) < (unsigned)WW;

    u64 kC1, kC3, kM7, kM1;
    PK2(kC1, C1, C1); PK2(kC3, C3, C3); PK2(kM7, -C7, -C7); PK2(kM1, -1.0f, -1.0f);

    StI s;
    #pragma unroll
    for (int i = 0; i < 7; ++i) { s.a[i][0] = 0ull; s.a[i][1] = 0ull; }
    #pragma unroll
    for (int k = 0; k < 4; ++k) { s.cp[k] = NEGINF; s.pm[k] = NEGINF; }
    s.bpp1 = 0; s.bpp2 = 0;

    const int rs = FIN ? (Y0 - 5) : (Y0 - 4);
    const float* pr = sp + (ptrdiff_t)rs * SSTR + c0;
    float4 LA, MA, RA, LB, MB, RB;
    if (GUARD) {
        bool rv0 = (unsigned)rs < (unsigned)HH;
        bool rv1 = (unsigned)(rs + 1) < (unsigned)HH;
        LA = (rv0 && Lok) ? *reinterpret_cast<const float4*>(pr - 4) : Z;
        MA = (rv0 && Mok) ? *reinterpret_cast<const float4*>(pr)     : Z;
        RA = (rv0 && Rok) ? *reinterpret_cast<const float4*>(pr + 4) : Z;
        LB = (rv1 && Lok) ? *reinterpret_cast<const float4*>(pr + SSTR - 4) : Z;
        MB = (rv1 && Mok) ? *reinterpret_cast<const float4*>(pr + SSTR)     : Z;
        RB = (rv1 && Rok) ? *reinterpret_cast<const float4*>(pr + SSTR + 4) : Z;
    } else {
        LA = *reinterpret_cast<const float4*>(pr - 4);
        MA = *reinterpret_cast<const float4*>(pr);
        RA = *reinterpret_cast<const float4*>(pr + 4);
        LB = *reinterpret_cast<const float4*>(pr + SSTR - 4);
        MB = *reinterpret_cast<const float4*>(pr + SSTR);
        RB = *reinterpret_cast<const float4*>(pr + SSTR + 4);
    }

    const float* p0 = pr + 2 * SSTR;
    int rload = rs + 2;
    int cr = rs - 4;          // incremented at top of each step (MY)
    float* wp = dp + (ptrdiff_t)(FIN ? (Y0 - 4) : (Y0 - 2)) * WSTR + c0;

    #define SIA(UU, VMf, WRf) \
        step_u<UU, FIN, VMf, WRf, MX, MY, GUARD, SSTR>(s, LA, MA, RA, p0, rload, cr, wp, cv, Lok, Mok, Rok, writeok, dup, kC1, kC3, kM7, kM1);
    #define SIB(UU, VMf, WRf) \
        step_u<UU, FIN, VMf, WRf, MX, MY, GUARD, SSTR>(s, LB, MB, RB, p0, rload, cr, wp, cv, Lok, Mok, Rok, writeok, dup, kC1, kC3, kM7, kM1);

    if (!FIN) {
        SIA(0,false,false) SIB(1,false,false) SIA(2,false,false) SIB(3,false,false)
        SIA(4,false,false) SIB(5,false,false) SIA(6,true,false)  SIB(0,true,false)
        #pragma unroll 1
        for (int g = 0; g < 2; ++g) {   // 14-step body (even)
            SIA(1,true,true) SIB(2,true,true) SIA(3,true,true) SIB(4,true,true)
            SIA(5,true,true) SIB(6,true,true) SIA(0,true,true)
            SIB(1,true,true) SIA(2,true,true) SIB(3,true,true) SIA(4,true,true)
            SIB(5,true,true) SIA(6,true,true) SIB(0,true,true)
        }
        SIA(1,true,true) SIB(2,true,true) SIA(3,true,true) SIB(4,true,true)
    } else {
        SIA(0,false,false) SIB(1,false,false) SIA(2,false,false) SIB(3,false,false)
        SIA(4,false,false) SIB(5,false,false) SIA(6,true,false)  SIB(0,true,false)
        SIA(1,true,false)  SIB(2,true,false)
        #pragma unroll 1
        for (int g = 0; g < 2; ++g) {
            SIA(3,true,true) SIB(4,true,true) SIA(5,true,true) SIB(6,true,true)
            SIA(0,true,true) SIB(1,true,true) SIA(2,true,true)
            SIB(3,true,true) SIA(4,true,true) SIB(5,true,true) SIA(6,true,true)
            SIB(0,true,true) SIA(1,true,true) SIB(2,true,true)
        }
        SIA(3,true,true) SIB(4,true,true) SIA(5,true,true) SIB(6,true,true)
    }
    #undef SIA
    #undef SIB
}

// ===== stage 1: reads unpadded x (guards on edge blocks), writes padded =====
__global__ void __launch_bounds__(32, 22) sweep1(const float* __restrict__ x,
                                                 float* __restrict__ dstPad)
{
    const int lane = threadIdx.x;
    const int sx = blockIdx.x;
    const int by = blockIdx.y;
    const int b  = blockIdx.z;
    const int Y0 = by * TH;
    const int c0 = 120 * sx - 4 + 4 * lane;
    const float* sp = x + (size_t)b * HH * WW;
    float* dp = dstPad + (size_t)b * PIMG + PADT * PW + PADL;

    if (sx >= 1 && sx <= 7 && by >= 1 && by <= 30)
        run_u<false, false, false, false, WW>(sp, dp, c0, Y0, lane, 0);
    else
        run_u<false, true, true, true, WW>(sp, dp, c0, Y0, lane, 0);
}

// ===== stages 2..4: padded source, no load guards, mask specialization =====
template<bool FIN>
__global__ void __launch_bounds__(32, 22) sweep2(const float* __restrict__ srcPad,
                                                 float* __restrict__ dst,
                                                 int dup)
{
    const int lane = threadIdx.x;
    const int sx = blockIdx.x;
    const int by = blockIdx.y;
    const int b  = blockIdx.z;
    const int Y0 = by * TH;
    const int c0 = 120 * sx - 4 + 4 * lane;
    const float* sp = srcPad + (size_t)b * PIMG + PADT * PW + PADL;
    float* dp = FIN ? (dst + (size_t)b * HH * WW)
                    : (dst + (size_t)b * PIMG + PADT * PW + PADL);

    const bool xe = (sx == 0) || (sx == 8);
    const bool ye = (by == 0) || (by == 31);

    if (!xe && !ye)      run_u<FIN, false, false, false, PW>(sp, dp, c0, Y0, lane, dup);
    else if (xe && !ye)  run_u<FIN, true,  false, false, PW>(sp, dp, c0, Y0, lane, dup);
    else if (!xe && ye)  run_u<FIN, false, true,  false, PW>(sp, dp, c0, Y0, lane, dup);
    else                 run_u<FIN, true,  true,  false, PW>(sp, dp, c0, Y0, lane, dup);
}

// ===== pad zeroing (idempotent, runs every launch) =====
#define PZ_R1 (16 * PW)          // 8 top + 8 bottom full rows
#define PZ_R2 (1024 * 80)        // per interior row: 8 left + 72 right
#define PZ_TOTAL (PZ_R1 + PZ_R2)

__global__ void padzero(float* __restrict__ bufA, float* __restrict__ bufB)
{
    int idx = blockIdx.x * 256 + threadIdx.x;
    if (idx >= PZ_TOTAL) return;
    float* buf = (blockIdx.z == 0) ? bufA : bufB;
    buf += (size_t)blockIdx.y * PIMG;

    int rp, c;
    if (idx < PZ_R1) {
        int row16 = idx / PW;
        c = idx - row16 * PW;
        rp = (row16 < 8) ? row16 : (8 + 1024 + (row16 - 8));
    } else {
        int j = idx - PZ_R1;
        int r = j / 80;
        int cj = j - r * 80;
        rp = 8 + r;
        c = (cj < 8) ? cj : (8 + 1024 + (cj - 8));
    }
    buf[(size_t)rp * PW + c] = 0.f;
}

extern "C" void kernel_launch(void* const* d_in, const int* in_sizes, int n_in,
                              void* d_out, int out_size)
{
    const float* x = (const float*)d_in[0];
    float* out = (float*)d_out;

    float *A, *B;
    cudaGetSymbolAddress((void**)&A, g_bufA);
    cudaGetSymbolAddress((void**)&B, g_bufB);

    dim3 grid(9, HH / TH, NB);
    int dup = (out_size >= 2 * NPIX) ? 1 : 0;

    dim3 pz((PZ_TOTAL + 255) / 256, NB, 2);
    padzero<<<pz, 256>>>(A, B);

    sweep1<<<grid, 32>>>(x, A);
    sweep2<false><<<grid, 32>>>(A, B, 0);
    sweep2<false><<<grid, 32>>>(B, A, 0);
    sweep2<true ><<<grid, 32>>>(A, out, dup);
}